// round 6
// baseline (speedup 1.0000x reference)
#include <cuda_runtime.h>
#include <cstdint>

#define BB 8
#define SS 2048
#define NN 512
#define DD 1024
#define WW 32

#define BIN_SHIFT 6                 // bin width 64 end-positions
#define NBINS (SS >> BIN_SHIFT)     // 32 bins per batch
#define QF4 64                      // float4 per quarter-row (256 floats)
#define MAXROWS (64 + WW - 1)       // 95 rows max per bin window
#define SPAN_THREADS 64

// Scratch (allocation-free: __device__ globals)
__device__ float g_logits[BB * SS];
__device__ float g_e[BB * SS];            // exp(logit - batch_max)
__device__ int   g_sorted[BB * NN];
__device__ int   g_binoff[BB * (NBINS + 1)];

// ---------------------------------------------------------------------------
// Kernel 1: logits[b*S+s] = dot(seq[row,:], att_w) + att_b.
// Persistent warps: att_w cached in registers, grid-stride over rows.
// ---------------------------------------------------------------------------
__global__ void __launch_bounds__(256) logits_kernel(
    const float* __restrict__ seq,
    const float* __restrict__ att_w,
    const float* __restrict__ att_b)
{
    const int lane = threadIdx.x & 31;
    const int gw   = (blockIdx.x * blockDim.x + threadIdx.x) >> 5;
    const int nw   = (gridDim.x * blockDim.x) >> 5;

    const float4* wv = reinterpret_cast<const float4*>(att_w);
    float4 w[8];
#pragma unroll
    for (int i = 0; i < 8; i++) w[i] = wv[lane + 32 * i];
    const float bias = att_b[0];

    for (int row = gw; row < BB * SS; row += nw) {
        const float4* r = reinterpret_cast<const float4*>(seq) + (size_t)row * (DD / 4);
        float acc = 0.0f;
#pragma unroll
        for (int i = 0; i < 8; i++) {
            float4 a = r[lane + 32 * i];
            acc += a.x * w[i].x + a.y * w[i].y + a.z * w[i].z + a.w * w[i].w;
        }
#pragma unroll
        for (int o = 16; o; o >>= 1)
            acc += __shfl_xor_sync(0xffffffffu, acc, o);
        if (lane == 0)
            g_logits[row] = acc + bias;
    }
}

// ---------------------------------------------------------------------------
// Kernel 2: per batch: C = max(logits), e[s] = exp(logits[s] - C).
// ---------------------------------------------------------------------------
__global__ void __launch_bounds__(256) escan_kernel()
{
    __shared__ float red[256];
    const int b   = blockIdx.x;
    const int tid = threadIdx.x;

    float v[8];
    float m = -1e30f;
#pragma unroll
    for (int i = 0; i < 8; i++) {
        v[i] = g_logits[b * SS + tid + 256 * i];
        m = fmaxf(m, v[i]);
    }
    red[tid] = m;
    __syncthreads();
#pragma unroll
    for (int s = 128; s; s >>= 1) {
        if (tid < s) red[tid] = fmaxf(red[tid], red[tid + s]);
        __syncthreads();
    }
    const float C = red[0];
#pragma unroll
    for (int i = 0; i < 8; i++)
        g_e[b * SS + tid + 256 * i] = __expf(v[i] - C);
}

// ---------------------------------------------------------------------------
// Kernel 3: counting-sort span ids into bins by end >> BIN_SHIFT.
// ---------------------------------------------------------------------------
__global__ void __launch_bounds__(NN) bin_kernel(const int* __restrict__ spans)
{
    __shared__ int hist[NBINS];
    __shared__ int offs[NBINS + 1];
    __shared__ int cursor[NBINS];

    const int b   = blockIdx.x;
    const int tid = threadIdx.x;

    if (tid < NBINS) hist[tid] = 0;
    __syncthreads();

    const int end = spans[(b * NN + tid) * 2 + 1];
    const int bin = end >> BIN_SHIFT;
    atomicAdd(&hist[bin], 1);
    __syncthreads();

    if (tid == 0) {
        int run = 0;
#pragma unroll
        for (int k = 0; k < NBINS; k++) { offs[k] = run; run += hist[k]; }
        offs[NBINS] = NN;
    }
    __syncthreads();
    if (tid < NBINS) cursor[tid] = offs[tid];
    __syncthreads();

    int pos = atomicAdd(&cursor[bin], 1);
    g_sorted[b * NN + pos] = tid;

    if (tid <= NBINS) g_binoff[b * (NBINS + 1) + tid] = offs[tid];
}

// ---------------------------------------------------------------------------
// Kernel 4: one block per (bin, D-quarter), 64 threads (one float4 column each).
//  A: stage window rows [bin*64-31, bin*64+63] (quarter slices) into SMEM.
//  B: in-place weighted prefix scan over rows: P[r] = sum_{t<=r} e[t]*v[t],
//     plus scalar e-prefix.
//  C: per span: out = (P[end] - P[start-1]) / (E[end] - E[start-1]).
//     Exact w.r.t. reference masking: masked softmax terms are exactly 0
//     (fp32 exp underflow), and span rows are contiguous (start >= 0 always).
// ---------------------------------------------------------------------------
extern __shared__ float4 sm_tile[];   // MAXROWS * QF4 float4 = 97280 B

__global__ void __launch_bounds__(SPAN_THREADS) span_kernel(
    const float* __restrict__ seq,
    const int*   __restrict__ spans,
    float*       __restrict__ out)
{
    __shared__ float sm_e[MAXROWS];
    __shared__ float sm_ep[MAXROWS];

    const int bing = blockIdx.x >> 2;
    const int dq   = blockIdx.x & 3;
    const int b    = bing >> 5;              // NBINS = 32
    const int lbin = bing & (NBINS - 1);

    const int s0 = g_binoff[b * (NBINS + 1) + lbin];
    const int s1 = g_binoff[b * (NBINS + 1) + lbin + 1];
    if (s0 == s1) return;

    const int tid = threadIdx.x;

    int lo = (lbin << BIN_SHIFT) - (WW - 1);
    if (lo < 0) lo = 0;
    const int hi   = (lbin << BIN_SHIFT) + 63;   // <= SS-1
    const int rows = hi - lo + 1;

    // --- A: stage tile (coalesced; independent loads, deep MLP) ---
    {
        const float4* gb = reinterpret_cast<const float4*>(seq)
                         + (size_t)b * SS * (DD / 4) + (size_t)lo * (DD / 4)
                         + dq * QF4 + tid;
#pragma unroll 8
        for (int r = 0; r < MAXROWS; r++) {
            if (r < rows)
                sm_tile[r * QF4 + tid] = gb[(size_t)r * (DD / 4)];
        }
        for (int r = tid; r < rows; r += SPAN_THREADS)
            sm_e[r] = g_e[b * SS + lo + r];
    }
    __syncthreads();

    // --- B: in-place weighted prefix scan (columns parallel, rows serial) ---
    {
        float4 acc = make_float4(0.f, 0.f, 0.f, 0.f);
        float  erun = 0.0f;
        for (int r = 0; r < rows; r++) {
            const float e = sm_e[r];
            float4 v = sm_tile[r * QF4 + tid];
            acc.x += e * v.x; acc.y += e * v.y; acc.z += e * v.z; acc.w += e * v.w;
            sm_tile[r * QF4 + tid] = acc;
            erun += e;
            if (tid == 0) sm_ep[r] = erun;
        }
    }
    __syncthreads();

    // --- C: spans: two SMEM row reads + one scaled store each ---
    float4* obase = reinterpret_cast<float4*>(out)
                  + (size_t)b * NN * (DD / 4) + dq * QF4 + tid;

    for (int si = s0; si < s1; si++) {
        const int n  = g_sorted[b * NN + si];
        const int2 se = reinterpret_cast<const int2*>(spans)[b * NN + n];
        const int rs = se.x - lo;          // >= 0 always
        const int re = se.y - lo;

        float4 Pe = sm_tile[re * QF4 + tid];
        float4 Pb = make_float4(0.f, 0.f, 0.f, 0.f);
        float  Eb = 0.0f;
        if (rs > 0) {
            Pb = sm_tile[(rs - 1) * QF4 + tid];
            Eb = sm_ep[rs - 1];
        }
        const float inv = 1.0f / (sm_ep[re] - Eb);

        float4 o;
        o.x = (Pe.x - Pb.x) * inv;
        o.y = (Pe.y - Pb.y) * inv;
        o.z = (Pe.z - Pb.z) * inv;
        o.w = (Pe.w - Pb.w) * inv;
        obase[(size_t)n * (DD / 4)] = o;
    }
}

// ---------------------------------------------------------------------------
// inputs: [0] sequence_tensor f32 (B,S,D)  [1] span_indices i32 (B,N,2)
//         [2] att_w f32 (D,1)              [3] att_b f32 (1)
// output: f32 (B,N,D)
// ---------------------------------------------------------------------------
extern "C" void kernel_launch(void* const* d_in, const int* in_sizes, int n_in,
                              void* d_out, int out_size)
{
    const float* seq   = (const float*)d_in[0];
    const int*   spans = (const int*)  d_in[1];
    const float* att_w = (const float*)d_in[2];
    const float* att_b = (const float*)d_in[3];
    float*       out   = (float*)d_out;

    (void)in_sizes; (void)n_in; (void)out_size;

    const int smem_bytes = MAXROWS * QF4 * (int)sizeof(float4);   // 97280
    static bool attr_done = false;
    if (!attr_done) {
        cudaFuncSetAttribute(span_kernel,
                             cudaFuncAttributeMaxDynamicSharedMemorySize, smem_bytes);
        attr_done = true;
    }

    logits_kernel<<<512, 256>>>(seq, att_w, att_b);
    escan_kernel<<<BB, 256>>>();
    bin_kernel<<<BB, NN>>>(spans);
    span_kernel<<<BB * NBINS * 4, SPAN_THREADS, smem_bytes>>>(seq, spans, out);
}

// round 7
// speedup vs baseline: 2.2996x; 2.2996x over previous
#include <cuda_runtime.h>
#include <cstdint>

#define BB 8
#define SS 2048
#define NN 512
#define DD 1024
#define WW 32

#define BIN_SHIFT 6                 // bin width 64 end-positions
#define NBINS (SS >> BIN_SHIFT)     // 32 bins per batch
#define QF  256                     // floats per quarter-row
#define QF4 64                      // float4 per quarter-row
#define MAXROWS (64 + WW - 1)       // 95 rows max per bin window
#define SPAN_THREADS 256

// Scratch (allocation-free: __device__ globals)
__device__ float g_logits[BB * SS];
__device__ float g_e[BB * SS];            // exp(logit - batch_max)
__device__ int   g_sorted[BB * NN];
__device__ int   g_binoff[BB * (NBINS + 1)];

// ---------------------------------------------------------------------------
// Kernel 1: logits = seq @ att_w + att_b. TWO rows per warp (MLP=16/thread)
// so in-flight bytes/SM cover DRAM latency at full bandwidth.
// ---------------------------------------------------------------------------
__global__ void __launch_bounds__(256) logits_kernel(
    const float* __restrict__ seq,
    const float* __restrict__ att_w,
    const float* __restrict__ att_b)
{
    const int lane  = threadIdx.x & 31;
    const int gwarp = (blockIdx.x * blockDim.x + threadIdx.x) >> 5;
    const int row0  = gwarp * 2;
    if (row0 >= BB * SS) return;

    const float4* wv = reinterpret_cast<const float4*>(att_w);
    const float4* r0 = reinterpret_cast<const float4*>(seq) + (size_t)row0 * (DD / 4);
    const float4* r1 = r0 + (DD / 4);

    float acc0 = 0.0f, acc1 = 0.0f;
#pragma unroll
    for (int i = 0; i < 8; i++) {
        float4 w = wv[lane + 32 * i];
        float4 a = r0[lane + 32 * i];
        float4 c = r1[lane + 32 * i];
        acc0 += a.x * w.x + a.y * w.y + a.z * w.z + a.w * w.w;
        acc1 += c.x * w.x + c.y * w.y + c.z * w.z + c.w * w.w;
    }
#pragma unroll
    for (int o = 16; o; o >>= 1) {
        acc0 += __shfl_xor_sync(0xffffffffu, acc0, o);
        acc1 += __shfl_xor_sync(0xffffffffu, acc1, o);
    }
    if (lane == 0) {
        const float bias = att_b[0];
        g_logits[row0]     = acc0 + bias;
        g_logits[row0 + 1] = acc1 + bias;
    }
}

// ---------------------------------------------------------------------------
// Kernel 2: per batch: C = max(logits), e[s] = exp(logits[s] - C).
// ---------------------------------------------------------------------------
__global__ void __launch_bounds__(256) escan_kernel()
{
    __shared__ float red[256];
    const int b   = blockIdx.x;
    const int tid = threadIdx.x;

    float v[8];
    float m = -1e30f;
#pragma unroll
    for (int i = 0; i < 8; i++) {
        v[i] = g_logits[b * SS + tid + 256 * i];
        m = fmaxf(m, v[i]);
    }
    red[tid] = m;
    __syncthreads();
#pragma unroll
    for (int s = 128; s; s >>= 1) {
        if (tid < s) red[tid] = fmaxf(red[tid], red[tid + s]);
        __syncthreads();
    }
    const float C = red[0];
#pragma unroll
    for (int i = 0; i < 8; i++)
        g_e[b * SS + tid + 256 * i] = __expf(v[i] - C);
}

// ---------------------------------------------------------------------------
// Kernel 3: counting-sort span ids into bins by end >> BIN_SHIFT.
// ---------------------------------------------------------------------------
__global__ void __launch_bounds__(NN) bin_kernel(const int* __restrict__ spans)
{
    __shared__ int hist[NBINS];
    __shared__ int offs[NBINS + 1];
    __shared__ int cursor[NBINS];

    const int b   = blockIdx.x;
    const int tid = threadIdx.x;

    if (tid < NBINS) hist[tid] = 0;
    __syncthreads();

    const int end = spans[(b * NN + tid) * 2 + 1];
    const int bin = end >> BIN_SHIFT;
    atomicAdd(&hist[bin], 1);
    __syncthreads();

    if (tid == 0) {
        int run = 0;
#pragma unroll
        for (int k = 0; k < NBINS; k++) { offs[k] = run; run += hist[k]; }
        offs[NBINS] = NN;
    }
    __syncthreads();
    if (tid < NBINS) cursor[tid] = offs[tid];
    __syncthreads();

    int pos = atomicAdd(&cursor[bin], 1);
    g_sorted[b * NN + pos] = tid;

    if (tid <= NBINS) g_binoff[b * (NBINS + 1) + tid] = offs[tid];
}

// ---------------------------------------------------------------------------
// Kernel 4: one 256-thread block per (bin, D-quarter).
//  A: stage window rows [bin*64-31, bin*64+63] quarter-slices into SMEM
//     (6080 float4, coalesced, ~24 loads/thread).
//  B: weighted prefix scan: thread owns ONE float column -> chain is pure
//     register FMA; rows serial (<=95), columns fully parallel.
//  C: per span: out = (P[end] - P[start-1]) / (E[end] - E[start-1]).
//     Exact vs reference masking: masked softmax terms are exactly 0 in fp32,
//     and span rows are contiguous with start >= lo always.
// ---------------------------------------------------------------------------
extern __shared__ float sm_tile[];   // MAXROWS * QF floats = 97280 B

__global__ void __launch_bounds__(SPAN_THREADS) span_kernel(
    const float* __restrict__ seq,
    const int*   __restrict__ spans,
    float*       __restrict__ out)
{
    __shared__ float sm_e[MAXROWS];
    __shared__ float sm_ep[MAXROWS];

    const int bing = blockIdx.x >> 2;
    const int dq   = blockIdx.x & 3;
    const int b    = bing >> 5;              // NBINS = 32
    const int lbin = bing & (NBINS - 1);

    const int s0 = g_binoff[b * (NBINS + 1) + lbin];
    const int s1 = g_binoff[b * (NBINS + 1) + lbin + 1];
    if (s0 == s1) return;

    const int tid = threadIdx.x;

    int lo = (lbin << BIN_SHIFT) - (WW - 1);
    if (lo < 0) lo = 0;
    const int hi   = (lbin << BIN_SHIFT) + 63;   // <= SS-1
    const int rows = hi - lo + 1;

    // --- A: stage tile ---
    {
        const float4* gb = reinterpret_cast<const float4*>(seq)
                         + (size_t)b * SS * (DD / 4) + (size_t)lo * (DD / 4) + dq * QF4;
        float4* sb = reinterpret_cast<float4*>(sm_tile);
        const int total = rows * QF4;
#pragma unroll 4
        for (int m = tid; m < total; m += SPAN_THREADS) {
            const int r = m >> 6;            // / QF4
            const int j = m & 63;
            sb[m] = gb[(size_t)r * (DD / 4) + j];
        }
        if (tid < rows)
            sm_e[tid] = g_e[b * SS + lo + tid];
    }
    __syncthreads();

    // --- B: weighted prefix scan, one float column per thread ---
    {
        float acc = 0.0f, erun = 0.0f;
#pragma unroll 4
        for (int r = 0; r < rows; r++) {
            const float e = sm_e[r];                 // broadcast, conflict-free
            acc += e * sm_tile[r * QF + tid];
            sm_tile[r * QF + tid] = acc;
            erun += e;
            if (tid == 0) sm_ep[r] = erun;
        }
    }
    __syncthreads();

    // --- C: two SMEM row reads + one coalesced 1KB store per span ---
    float* obase = out + (size_t)b * NN * DD + dq * QF + tid;

    for (int si = s0; si < s1; si++) {
        const int n   = g_sorted[b * NN + si];
        const int2 se = reinterpret_cast<const int2*>(spans)[b * NN + n];
        const int rs  = se.x - lo;         // >= 0 always
        const int re  = se.y - lo;

        float Pe = sm_tile[re * QF + tid];
        float Pb = 0.0f, Eb = 0.0f;
        if (rs > 0) {
            Pb = sm_tile[(rs - 1) * QF + tid];
            Eb = sm_ep[rs - 1];
        }
        const float inv = 1.0f / (sm_ep[re] - Eb);
        obase[(size_t)n * DD] = (Pe - Pb) * inv;
    }
}

// ---------------------------------------------------------------------------
// inputs: [0] sequence_tensor f32 (B,S,D)  [1] span_indices i32 (B,N,2)
//         [2] att_w f32 (D,1)              [3] att_b f32 (1)
// output: f32 (B,N,D)
// ---------------------------------------------------------------------------
extern "C" void kernel_launch(void* const* d_in, const int* in_sizes, int n_in,
                              void* d_out, int out_size)
{
    const float* seq   = (const float*)d_in[0];
    const int*   spans = (const int*)  d_in[1];
    const float* att_w = (const float*)d_in[2];
    const float* att_b = (const float*)d_in[3];
    float*       out   = (float*)d_out;

    (void)in_sizes; (void)n_in; (void)out_size;

    const int smem_bytes = MAXROWS * QF * (int)sizeof(float);   // 97280
    static bool attr_done = false;
    if (!attr_done) {
        cudaFuncSetAttribute(span_kernel,
                             cudaFuncAttributeMaxDynamicSharedMemorySize, smem_bytes);
        attr_done = true;
    }

    logits_kernel<<<(BB * SS) / 16, 256>>>(seq, att_w, att_b);   // 2 rows/warp
    escan_kernel<<<BB, 256>>>();
    bin_kernel<<<BB, NN>>>(spans);
    span_kernel<<<BB * NBINS * 4, SPAN_THREADS, smem_bytes>>>(seq, spans, out);
}

// round 8
// speedup vs baseline: 2.8065x; 1.2204x over previous
#include <cuda_runtime.h>
#include <cstdint>

#define BB 8
#define SS 2048
#define NN 512
#define DD 1024
#define WW 32

#define BIN_SHIFT 6                 // bin width 64 end-positions
#define NBINS (SS >> BIN_SHIFT)     // 32 bins per batch
#define QF  256                     // floats per quarter-row
#define MAXROWS (64 + WW - 1)       // 95 rows max per bin window
#define SPAN_THREADS 256
#define CHUNK 128                   // span-metadata chunk

// Scratch (allocation-free: __device__ globals)
__device__ float g_logits[BB * SS];
__device__ float g_e[BB * SS];            // exp(logit - batch_max)
__device__ int   g_sorted[BB * NN];
__device__ int   g_binoff[BB * (NBINS + 1)];

// ---------------------------------------------------------------------------
// Kernel 1: logits = seq @ att_w + att_b. Two rows per warp (MLP=16/thread).
// ---------------------------------------------------------------------------
__global__ void __launch_bounds__(256) logits_kernel(
    const float* __restrict__ seq,
    const float* __restrict__ att_w,
    const float* __restrict__ att_b)
{
    const int lane  = threadIdx.x & 31;
    const int gwarp = (blockIdx.x * blockDim.x + threadIdx.x) >> 5;
    const int row0  = gwarp * 2;
    if (row0 >= BB * SS) return;

    const float4* wv = reinterpret_cast<const float4*>(att_w);
    const float4* r0 = reinterpret_cast<const float4*>(seq) + (size_t)row0 * (DD / 4);
    const float4* r1 = r0 + (DD / 4);

    float acc0 = 0.0f, acc1 = 0.0f;
#pragma unroll
    for (int i = 0; i < 8; i++) {
        float4 w = wv[lane + 32 * i];
        float4 a = r0[lane + 32 * i];
        float4 c = r1[lane + 32 * i];
        acc0 += a.x * w.x + a.y * w.y + a.z * w.z + a.w * w.w;
        acc1 += c.x * w.x + c.y * w.y + c.z * w.z + c.w * w.w;
    }
#pragma unroll
    for (int o = 16; o; o >>= 1) {
        acc0 += __shfl_xor_sync(0xffffffffu, acc0, o);
        acc1 += __shfl_xor_sync(0xffffffffu, acc1, o);
    }
    if (lane == 0) {
        const float bias = att_b[0];
        g_logits[row0]     = acc0 + bias;
        g_logits[row0 + 1] = acc1 + bias;
    }
}

// ---------------------------------------------------------------------------
// Kernel 2: per batch: C = max(logits), e[s] = exp(logits[s] - C).
// ---------------------------------------------------------------------------
__global__ void __launch_bounds__(256) escan_kernel()
{
    __shared__ float red[256];
    const int b   = blockIdx.x;
    const int tid = threadIdx.x;

    float v[8];
    float m = -1e30f;
#pragma unroll
    for (int i = 0; i < 8; i++) {
        v[i] = g_logits[b * SS + tid + 256 * i];
        m = fmaxf(m, v[i]);
    }
    red[tid] = m;
    __syncthreads();
#pragma unroll
    for (int s = 128; s; s >>= 1) {
        if (tid < s) red[tid] = fmaxf(red[tid], red[tid + s]);
        __syncthreads();
    }
    const float C = red[0];
#pragma unroll
    for (int i = 0; i < 8; i++)
        g_e[b * SS + tid + 256 * i] = __expf(v[i] - C);
}

// ---------------------------------------------------------------------------
// Kernel 3: counting-sort span ids into bins by end >> BIN_SHIFT.
// ---------------------------------------------------------------------------
__global__ void __launch_bounds__(NN) bin_kernel(const int* __restrict__ spans)
{
    __shared__ int hist[NBINS];
    __shared__ int offs[NBINS + 1];
    __shared__ int cursor[NBINS];

    const int b   = blockIdx.x;
    const int tid = threadIdx.x;

    if (tid < NBINS) hist[tid] = 0;
    __syncthreads();

    const int end = spans[(b * NN + tid) * 2 + 1];
    const int bin = end >> BIN_SHIFT;
    atomicAdd(&hist[bin], 1);
    __syncthreads();

    if (tid == 0) {
        int run = 0;
#pragma unroll
        for (int k = 0; k < NBINS; k++) { offs[k] = run; run += hist[k]; }
        offs[NBINS] = NN;
    }
    __syncthreads();
    if (tid < NBINS) cursor[tid] = offs[tid];
    __syncthreads();

    int pos = atomicAdd(&cursor[bin], 1);
    g_sorted[b * NN + pos] = tid;

    if (tid <= NBINS) g_binoff[b * (NBINS + 1) + tid] = offs[tid];
}

// ---------------------------------------------------------------------------
// Kernel 4: one 256-thread block per (bin, D-quarter).
//  Fused scan: stream window rows [bin*64-31, bin*64+63] straight from global
//  (L2-resident after kernel 1) with 8-deep register prefetch; write weighted
//  prefix P[r] = sum_{t<=r} e[t]*v[t] to SMEM once. Scalar e-prefix kept per
//  thread; thread 0 stores it.
//  Phase C: span metadata (n, rs, re) is chunk-loaded into SMEM in parallel
//  (one latency round), then each span is 2 conflict-free LDS + 1 coalesced
//  STG with independent iterations.
//  out = (P[end] - P[start-1]) / (E[end] - E[start-1]) -- exact vs reference
//  masking: masked softmax terms are exactly 0 in fp32, rows are contiguous,
//  start >= lo always.
// ---------------------------------------------------------------------------
extern __shared__ float sm_p[];   // MAXROWS * QF floats = 97280 B

__global__ void __launch_bounds__(SPAN_THREADS) span_kernel(
    const float* __restrict__ seq,
    const int*   __restrict__ spans,
    float*       __restrict__ out)
{
    __shared__ float sm_e[MAXROWS];
    __shared__ float sm_ep[MAXROWS];
    __shared__ int   c_n[CHUNK];
    __shared__ int   c_rs[CHUNK];
    __shared__ int   c_re[CHUNK];

    const int bing = blockIdx.x >> 2;
    const int dq   = blockIdx.x & 3;
    const int b    = bing >> 5;              // NBINS = 32
    const int lbin = bing & (NBINS - 1);

    const int s0 = g_binoff[b * (NBINS + 1) + lbin];
    const int s1 = g_binoff[b * (NBINS + 1) + lbin + 1];
    if (s0 == s1) return;

    const int tid = threadIdx.x;

    int lo = (lbin << BIN_SHIFT) - (WW - 1);
    if (lo < 0) lo = 0;
    const int hi   = (lbin << BIN_SHIFT) + 63;   // <= SS-1
    const int rows = hi - lo + 1;

    // prologue: e values for the window
    if (tid < rows)
        sm_e[tid] = g_e[b * SS + lo + tid];
    __syncthreads();

    // fused global->SMEM weighted prefix scan, one float column per thread
    {
        const float* gcol = seq + ((size_t)b * SS + lo) * DD + dq * QF + tid;
        float acc = 0.0f, erun = 0.0f;
        int r = 0;
        for (; r + 8 <= rows; r += 8) {
            float v[8];
#pragma unroll
            for (int k = 0; k < 8; k++)
                v[k] = gcol[(r + k) * DD];
#pragma unroll
            for (int k = 0; k < 8; k++) {
                const float e = sm_e[r + k];
                acc = fmaf(e, v[k], acc);
                sm_p[(r + k) * QF + tid] = acc;
                erun += e;
                if (tid == 0) sm_ep[r + k] = erun;
            }
        }
        for (; r < rows; r++) {
            const float e = sm_e[r];
            acc = fmaf(e, gcol[r * DD], acc);
            sm_p[r * QF + tid] = acc;
            erun += e;
            if (tid == 0) sm_ep[r] = erun;
        }
    }
    __syncthreads();

    // phase C: chunked metadata load + independent span emits
    float* obase = out + (size_t)b * NN * DD + dq * QF + tid;
    const int2* spans2 = reinterpret_cast<const int2*>(spans) + b * NN;

    for (int base = s0; base < s1; base += CHUNK) {
        const int cnt = (s1 - base) < CHUNK ? (s1 - base) : CHUNK;
        if (tid < cnt) {
            const int n  = g_sorted[b * NN + base + tid];
            const int2 se = spans2[n];
            c_n[tid]  = n;
            c_rs[tid] = se.x - lo;     // >= 0 always
            c_re[tid] = se.y - lo;
        }
        __syncthreads();

#pragma unroll 2
        for (int k = 0; k < cnt; k++) {
            const int n  = c_n[k];
            const int rs = c_rs[k];
            const int re = c_re[k];

            const float Pe = sm_p[re * QF + tid];
            float Pb = 0.0f, Eb = 0.0f;
            if (rs > 0) {
                Pb = sm_p[(rs - 1) * QF + tid];
                Eb = sm_ep[rs - 1];
            }
            const float inv = __fdividef(1.0f, sm_ep[re] - Eb);
            obase[(size_t)n * DD] = (Pe - Pb) * inv;
        }
        __syncthreads();
    }
}

// ---------------------------------------------------------------------------
// inputs: [0] sequence_tensor f32 (B,S,D)  [1] span_indices i32 (B,N,2)
//         [2] att_w f32 (D,1)              [3] att_b f32 (1)
// output: f32 (B,N,D)
// ---------------------------------------------------------------------------
extern "C" void kernel_launch(void* const* d_in, const int* in_sizes, int n_in,
                              void* d_out, int out_size)
{
    const float* seq   = (const float*)d_in[0];
    const int*   spans = (const int*)  d_in[1];
    const float* att_w = (const float*)d_in[2];
    const float* att_b = (const float*)d_in[3];
    float*       out   = (float*)d_out;

    (void)in_sizes; (void)n_in; (void)out_size;

    const int smem_bytes = MAXROWS * QF * (int)sizeof(float);   // 97280
    static bool attr_done = false;
    if (!attr_done) {
        cudaFuncSetAttribute(span_kernel,
                             cudaFuncAttributeMaxDynamicSharedMemorySize, smem_bytes);
        attr_done = true;
    }

    logits_kernel<<<(BB * SS) / 16, 256>>>(seq, att_w, att_b);   // 2 rows/warp
    escan_kernel<<<BB, 256>>>();
    bin_kernel<<<BB, NN>>>(spans);
    span_kernel<<<BB * NBINS * 4, SPAN_THREADS, smem_bytes>>>(seq, spans, out);
}

// round 9
// speedup vs baseline: 3.3677x; 1.2000x over previous
#include <cuda_runtime.h>
#include <cstdint>

#define BB 8
#define SS 2048
#define NN 512
#define DD 1024
#define WW 32

#define BIN_SHIFT 6                 // bin width 64 end-positions
#define NBINS (SS >> BIN_SHIFT)     // 32 bins per batch
#define QF  256                     // floats per quarter-row
#define QF4 64                      // float4 per quarter-row
#define MAXROWS (64 + WW - 1)       // 95 rows max per bin window
#define SPAN_THREADS 256
#define CHUNK 128                   // span-metadata chunk

#define CP_ASYNC16(dst_u32, src_ptr) \
    asm volatile("cp.async.ca.shared.global [%0], [%1], 16;" \
                 :: "r"(dst_u32), "l"(src_ptr))
#define CP_ASYNC_COMMIT() asm volatile("cp.async.commit_group;" ::: "memory")
#define CP_ASYNC_WAIT0()  asm volatile("cp.async.wait_group 0;" ::: "memory")

// Scratch (allocation-free: __device__ globals)
__device__ float g_logits[BB * SS];
__device__ float g_e[BB * SS];            // exp(logit - batch_max)
__device__ int   g_sorted[BB * NN];
__device__ int   g_binoff[BB * (NBINS + 1)];

// ---------------------------------------------------------------------------
// Kernel 1: logits = seq @ att_w + att_b. Two rows per warp (MLP=16/thread).
// ---------------------------------------------------------------------------
__global__ void __launch_bounds__(256) logits_kernel(
    const float* __restrict__ seq,
    const float* __restrict__ att_w,
    const float* __restrict__ att_b)
{
    const int lane  = threadIdx.x & 31;
    const int gwarp = (blockIdx.x * blockDim.x + threadIdx.x) >> 5;
    const int row0  = gwarp * 2;
    if (row0 >= BB * SS) return;

    const float4* wv = reinterpret_cast<const float4*>(att_w);
    const float4* r0 = reinterpret_cast<const float4*>(seq) + (size_t)row0 * (DD / 4);
    const float4* r1 = r0 + (DD / 4);

    float acc0 = 0.0f, acc1 = 0.0f;
#pragma unroll
    for (int i = 0; i < 8; i++) {
        float4 w = wv[lane + 32 * i];
        float4 a = r0[lane + 32 * i];
        float4 c = r1[lane + 32 * i];
        acc0 += a.x * w.x + a.y * w.y + a.z * w.z + a.w * w.w;
        acc1 += c.x * w.x + c.y * w.y + c.z * w.z + c.w * w.w;
    }
#pragma unroll
    for (int o = 16; o; o >>= 1) {
        acc0 += __shfl_xor_sync(0xffffffffu, acc0, o);
        acc1 += __shfl_xor_sync(0xffffffffu, acc1, o);
    }
    if (lane == 0) {
        const float bias = att_b[0];
        g_logits[row0]     = acc0 + bias;
        g_logits[row0 + 1] = acc1 + bias;
    }
}

// ---------------------------------------------------------------------------
// Kernel 2: per batch: C = max(logits), e[s] = exp(logits[s] - C).
// ---------------------------------------------------------------------------
__global__ void __launch_bounds__(256) escan_kernel()
{
    __shared__ float red[256];
    const int b   = blockIdx.x;
    const int tid = threadIdx.x;

    float v[8];
    float m = -1e30f;
#pragma unroll
    for (int i = 0; i < 8; i++) {
        v[i] = g_logits[b * SS + tid + 256 * i];
        m = fmaxf(m, v[i]);
    }
    red[tid] = m;
    __syncthreads();
#pragma unroll
    for (int s = 128; s; s >>= 1) {
        if (tid < s) red[tid] = fmaxf(red[tid], red[tid + s]);
        __syncthreads();
    }
    const float C = red[0];
#pragma unroll
    for (int i = 0; i < 8; i++)
        g_e[b * SS + tid + 256 * i] = __expf(v[i] - C);
}

// ---------------------------------------------------------------------------
// Kernel 3: counting-sort span ids into bins by end >> BIN_SHIFT.
// ---------------------------------------------------------------------------
__global__ void __launch_bounds__(NN) bin_kernel(const int* __restrict__ spans)
{
    __shared__ int hist[NBINS];
    __shared__ int offs[NBINS + 1];
    __shared__ int cursor[NBINS];

    const int b   = blockIdx.x;
    const int tid = threadIdx.x;

    if (tid < NBINS) hist[tid] = 0;
    __syncthreads();

    const int end = spans[(b * NN + tid) * 2 + 1];
    const int bin = end >> BIN_SHIFT;
    atomicAdd(&hist[bin], 1);
    __syncthreads();

    if (tid == 0) {
        int run = 0;
#pragma unroll
        for (int k = 0; k < NBINS; k++) { offs[k] = run; run += hist[k]; }
        offs[NBINS] = NN;
    }
    __syncthreads();
    if (tid < NBINS) cursor[tid] = offs[tid];
    __syncthreads();

    int pos = atomicAdd(&cursor[bin], 1);
    g_sorted[b * NN + pos] = tid;

    if (tid <= NBINS) g_binoff[b * (NBINS + 1) + tid] = offs[tid];
}

// ---------------------------------------------------------------------------
// Kernel 4: one 256-thread block per (bin, D-quarter).
//  Stage: entire window tile (<=95KB) via cp.async (huge MLP, no reg
//  round-trip); overlap e-vector + first span-metadata chunk loads under it.
//  Scan:  SMEM->SMEM weighted prefix (29-cyc LDS instead of 577-cyc LDG):
//         P[r] = sum_{t<=r} e[t]*v[t], in place; scalar e-prefix by thread 0.
//  Emit:  out = (P[end]-P[start-1]) / (E[end]-E[start-1]).
//  Exact vs reference: masked softmax terms are exactly 0 in fp32; span rows
//  contiguous, start >= lo always.
// ---------------------------------------------------------------------------
extern __shared__ float sm_p[];   // MAXROWS * QF floats = 97280 B

__global__ void __launch_bounds__(SPAN_THREADS) span_kernel(
    const float* __restrict__ seq,
    const int*   __restrict__ spans,
    float*       __restrict__ out)
{
    __shared__ float sm_e[MAXROWS];
    __shared__ float sm_ep[MAXROWS];
    __shared__ int   c_n[CHUNK];
    __shared__ int   c_rs[CHUNK];
    __shared__ int   c_re[CHUNK];

    const int bing = blockIdx.x >> 2;
    const int dq   = blockIdx.x & 3;
    const int b    = bing >> 5;              // NBINS = 32
    const int lbin = bing & (NBINS - 1);

    const int s0 = g_binoff[b * (NBINS + 1) + lbin];
    const int s1 = g_binoff[b * (NBINS + 1) + lbin + 1];
    if (s0 == s1) return;

    const int tid = threadIdx.x;

    int lo = (lbin << BIN_SHIFT) - (WW - 1);
    if (lo < 0) lo = 0;
    const int hi   = (lbin << BIN_SHIFT) + 63;   // <= SS-1
    const int rows = hi - lo + 1;

    // --- stage tile via cp.async (all rows in flight at once) ---
    {
        const char* gb = reinterpret_cast<const char*>(
            seq + ((size_t)b * SS + lo) * DD + dq * QF);
        uint32_t sbase = (uint32_t)__cvta_generic_to_shared(sm_p);
        const int total = rows * QF4;            // float4 count
#pragma unroll 4
        for (int m = tid; m < total; m += SPAN_THREADS) {
            const int r = m >> 6;                // / QF4
            const int j = m & 63;
            CP_ASYNC16(sbase + (unsigned)m * 16u,
                       gb + (size_t)r * (DD * 4) + (size_t)j * 16);
        }
        CP_ASYNC_COMMIT();
    }

    // --- overlapped: e values + first metadata chunk ---
    if (tid < rows)
        sm_e[tid] = g_e[b * SS + lo + tid];

    const int2* spans2 = reinterpret_cast<const int2*>(spans) + b * NN;
    const int cnt0 = (s1 - s0) < CHUNK ? (s1 - s0) : CHUNK;
    if (tid < cnt0) {
        const int n   = g_sorted[b * NN + s0 + tid];
        const int2 se = spans2[n];
        c_n[tid]  = n;
        c_rs[tid] = se.x - lo;      // >= 0 always
        c_re[tid] = se.y - lo;
    }

    CP_ASYNC_WAIT0();
    __syncthreads();

    // --- SMEM->SMEM weighted prefix scan, one float column per thread ---
    {
        float acc = 0.0f, erun = 0.0f;
        int r = 0;
        for (; r + 4 <= rows; r += 4) {
            float v0 = sm_p[(r + 0) * QF + tid];
            float v1 = sm_p[(r + 1) * QF + tid];
            float v2 = sm_p[(r + 2) * QF + tid];
            float v3 = sm_p[(r + 3) * QF + tid];
            float e0 = sm_e[r + 0], e1 = sm_e[r + 1];
            float e2 = sm_e[r + 2], e3 = sm_e[r + 3];
            acc = fmaf(e0, v0, acc); sm_p[(r + 0) * QF + tid] = acc;
            acc = fmaf(e1, v1, acc); sm_p[(r + 1) * QF + tid] = acc;
            acc = fmaf(e2, v2, acc); sm_p[(r + 2) * QF + tid] = acc;
            acc = fmaf(e3, v3, acc); sm_p[(r + 3) * QF + tid] = acc;
            if (tid == 0) {
                erun += e0; sm_ep[r + 0] = erun;
                erun += e1; sm_ep[r + 1] = erun;
                erun += e2; sm_ep[r + 2] = erun;
                erun += e3; sm_ep[r + 3] = erun;
            }
        }
        for (; r < rows; r++) {
            const float e = sm_e[r];
            acc = fmaf(e, sm_p[r * QF + tid], acc);
            sm_p[r * QF + tid] = acc;
            if (tid == 0) { erun += e; sm_ep[r] = erun; }
        }
    }
    __syncthreads();

    // --- emit spans: 2 conflict-free LDS + 1 coalesced 1KB STG each ---
    float* obase = out + (size_t)b * NN * DD + dq * QF + tid;

    // chunk 0 (metadata already loaded)
#pragma unroll 2
    for (int k = 0; k < cnt0; k++) {
        const int n  = c_n[k];
        const int rs = c_rs[k];
        const int re = c_re[k];
        const float Pe = sm_p[re * QF + tid];
        float Pb = 0.0f, Eb = 0.0f;
        if (rs > 0) {
            Pb = sm_p[(rs - 1) * QF + tid];
            Eb = sm_ep[rs - 1];
        }
        const float inv = __fdividef(1.0f, sm_ep[re] - Eb);
        obase[(size_t)n * DD] = (Pe - Pb) * inv;
    }

    // rare overflow chunks
    for (int base = s0 + CHUNK; base < s1; base += CHUNK) {
        const int cnt = (s1 - base) < CHUNK ? (s1 - base) : CHUNK;
        __syncthreads();
        if (tid < cnt) {
            const int n   = g_sorted[b * NN + base + tid];
            const int2 se = spans2[n];
            c_n[tid]  = n;
            c_rs[tid] = se.x - lo;
            c_re[tid] = se.y - lo;
        }
        __syncthreads();
        for (int k = 0; k < cnt; k++) {
            const int n  = c_n[k];
            const int rs = c_rs[k];
            const int re = c_re[k];
            const float Pe = sm_p[re * QF + tid];
            float Pb = 0.0f, Eb = 0.0f;
            if (rs > 0) {
                Pb = sm_p[(rs - 1) * QF + tid];
                Eb = sm_ep[rs - 1];
            }
            const float inv = __fdividef(1.0f, sm_ep[re] - Eb);
            obase[(size_t)n * DD] = (Pe - Pb) * inv;
        }
    }
}

// ---------------------------------------------------------------------------
// inputs: [0] sequence_tensor f32 (B,S,D)  [1] span_indices i32 (B,N,2)
//         [2] att_w f32 (D,1)              [3] att_b f32 (1)
// output: f32 (B,N,D)
// ---------------------------------------------------------------------------
extern "C" void kernel_launch(void* const* d_in, const int* in_sizes, int n_in,
                              void* d_out, int out_size)
{
    const float* seq   = (const float*)d_in[0];
    const int*   spans = (const int*)  d_in[1];
    const float* att_w = (const float*)d_in[2];
    const float* att_b = (const float*)d_in[3];
    float*       out   = (float*)d_out;

    (void)in_sizes; (void)n_in; (void)out_size;

    const int smem_bytes = MAXROWS * QF * (int)sizeof(float);   // 97280
    static bool attr_done = false;
    if (!attr_done) {
        cudaFuncSetAttribute(span_kernel,
                             cudaFuncAttributeMaxDynamicSharedMemorySize, smem_bytes);
        attr_done = true;
    }

    logits_kernel<<<(BB * SS) / 16, 256>>>(seq, att_w, att_b);   // 2 rows/warp
    escan_kernel<<<BB, 256>>>();
    bin_kernel<<<BB, NN>>>(spans);
    span_kernel<<<BB * NBINS * 4, SPAN_THREADS, smem_bytes>>>(seq, spans, out);
}